// round 1
// baseline (speedup 1.0000x reference)
#include <cuda_runtime.h>
#include <cuda_bf16.h>

// Contamination: out = 0.8*x + 0.2 * avg(valid 8 neighbors at offsets (±8, ±8), (0,±8), (±8,0))
// x: [B=8, C=32, H=512, W=512] fp32. k=8 fixed.
//
// Strategy: float4 vectorized, 2D CTA tile 128 cols x 32 rows, 256 threads
// (32x8), 4 rows per thread (stride 8 in y). Neighbor reuse is served by L1
// (tile working set ~28 KB << 228 KB L1), keeping L2 traffic ~1.7x compulsory
// and HBM at the 512 MiB floor.

namespace {

constexpr int H = 512;
constexpr int W = 512;
constexpr int K = 8;            // kernel_size (block size)
constexpr int W4 = W / 4;       // 128 float4 per row

__device__ __forceinline__ float4 f4add(float4 a, float4 b) {
    return make_float4(a.x + b.x, a.y + b.y, a.z + b.z, a.w + b.w);
}

__global__ __launch_bounds__(256, 8)
void contam_kernel(const float4* __restrict__ in, float4* __restrict__ out) {
    const int c4   = blockIdx.x * 32 + threadIdx.x;   // float4 column, 0..127
    const int row0 = blockIdx.y * 32 + threadIdx.y;   // base row of this thread
    const long plane = blockIdx.z;                    // b*C + c, 0..255

    const float4* __restrict__ pin  = in  + plane * (long)(H * W4);
    float4* __restrict__       pout = out + plane * (long)(H * W4);

    // Column-neighbor validity is uniform across the 4 lanes of a float4
    // because K=8 is a multiple of 4: left valid iff 4*c4 - 8 >= 0.
    const bool hasL = (c4 >= 2);
    const bool hasR = (c4 <= W4 - 3);
    const int  nc   = 1 + (int)hasL + (int)hasR;

    #pragma unroll
    for (int ry = 0; ry < 4; ry++) {
        const int h = row0 + ry * 8;
        const bool hasT = (h >= K);
        const bool hasB = (h < H - K);
        const int  nr   = 1 + (int)hasT + (int)hasB;
        const float inv_cnt = 1.0f / (float)(nr * nc - 1);

        const float4* rC = pin + (long)h * W4;

        float4 acc = make_float4(0.f, 0.f, 0.f, 0.f);
        float4 ctr = rC[c4];

        // top row
        if (hasT) {
            const float4* r = rC - K * W4;
            acc = f4add(acc, r[c4]);
            if (hasL) acc = f4add(acc, r[c4 - 2]);
            if (hasR) acc = f4add(acc, r[c4 + 2]);
        }
        // center row (center element added then subtracted via nsum)
        {
            acc = f4add(acc, ctr);
            if (hasL) acc = f4add(acc, rC[c4 - 2]);
            if (hasR) acc = f4add(acc, rC[c4 + 2]);
        }
        // bottom row
        if (hasB) {
            const float4* r = rC + K * W4;
            acc = f4add(acc, r[c4]);
            if (hasL) acc = f4add(acc, r[c4 - 2]);
            if (hasR) acc = f4add(acc, r[c4 + 2]);
        }

        // nsum = acc - ctr;  out = 0.8*ctr + 0.2*nsum/count
        float4 o;
        o.x = 0.8f * ctr.x + 0.2f * (acc.x - ctr.x) * inv_cnt;
        o.y = 0.8f * ctr.y + 0.2f * (acc.y - ctr.y) * inv_cnt;
        o.z = 0.8f * ctr.z + 0.2f * (acc.z - ctr.z) * inv_cnt;
        o.w = 0.8f * ctr.w + 0.2f * (acc.w - ctr.w) * inv_cnt;

        pout[(long)h * W4 + c4] = o;
    }
}

} // namespace

extern "C" void kernel_launch(void* const* d_in, const int* in_sizes, int n_in,
                              void* d_out, int out_size) {
    const float4* x = (const float4*)d_in[0];
    float4* out = (float4*)d_out;

    // planes = B*C = total_elems / (H*W)
    const int planes = in_sizes[0] / (H * W);   // 256

    dim3 block(32, 8, 1);
    dim3 grid(W4 / 32, H / 32, planes);         // (4, 16, 256)
    contam_kernel<<<grid, block>>>(x, out);
}